// round 1
// baseline (speedup 1.0000x reference)
#include <cuda_runtime.h>
#include <cuda_bf16.h>
#include <math.h>

// GCNII forward: N=50000 nodes, E=800000 edges, IN=512, H=128, C=40, L=8.
// Pipeline per launch:
//   1. Build CSR (by dst) on device: zero -> hist -> blocksum -> scan -> fill
//   2. Fold identity-mapping into per-layer weights: W'_l = beta_l*W_l + (1-beta_l)*I
//   3. x = h0 = relu(features @ w_fc0 + b_fc0)           (tiled SGEMM)
//   4. 8x { sup = 0.9*(A_hat x) + 0.1*h0 (warp-per-node CSR gather);
//           x = relu(sup @ W'_l) }                        (tiled SGEMM)
//   5. out = x @ w_fc1 + b_fc1

#define NNODES 50000
#define NEDGES 800000
#define DIN 512
#define DH 128
#define DC 40
#define NLAYERS 8
#define NSCANB 49   // ceil(50000/1024)

// ---------------- device scratch (no allocation allowed) ----------------
__device__ __align__(16) float g_x   [NNODES * DH];
__device__ __align__(16) float g_h0  [NNODES * DH];
__device__ __align__(16) float g_sup [NNODES * DH];
__device__ __align__(16) float g_Wp  [NLAYERS * DH * DH];
__device__ int   g_rowstart[NNODES + 1];
__device__ int   g_cursor  [NNODES];
__device__ int   g_col     [NEDGES];
__device__ float g_wval    [NEDGES];
__device__ int   g_blocksum[64];

struct Betas { float b[NLAYERS]; };

// ---------------- CSR build ----------------
__global__ void k_zero() {
    int i = blockIdx.x * blockDim.x + threadIdx.x;
    if (i < NNODES) g_cursor[i] = 0;
}

__global__ void k_hist(const int* __restrict__ dst) {
    int e = blockIdx.x * blockDim.x + threadIdx.x;
    if (e < NEDGES) atomicAdd(&g_cursor[dst[e]], 1);
}

__global__ void k_blocksum() {
    __shared__ int s[1024];
    int idx = blockIdx.x * 1024 + threadIdx.x;
    s[threadIdx.x] = (idx < NNODES) ? g_cursor[idx] : 0;
    __syncthreads();
    for (int off = 512; off > 0; off >>= 1) {
        if (threadIdx.x < off) s[threadIdx.x] += s[threadIdx.x + off];
        __syncthreads();
    }
    if (threadIdx.x == 0) g_blocksum[blockIdx.x] = s[0];
}

__global__ void k_scan_small() {
    // single thread: exclusive scan over 49 block sums
    int run = 0;
    for (int b = 0; b < NSCANB; b++) {
        int t = g_blocksum[b];
        g_blocksum[b] = run;
        run += t;
    }
    g_rowstart[NNODES] = run;  // == NEDGES
}

__global__ void k_scan_final() {
    __shared__ int s[1024];
    int tid = threadIdx.x;
    int idx = blockIdx.x * 1024 + tid;
    int v = (idx < NNODES) ? g_cursor[idx] : 0;
    s[tid] = v;
    __syncthreads();
    for (int off = 1; off < 1024; off <<= 1) {
        int t = (tid >= off) ? s[tid - off] : 0;
        __syncthreads();
        s[tid] += t;
        __syncthreads();
    }
    int excl = ((tid > 0) ? s[tid - 1] : 0) + g_blocksum[blockIdx.x];
    if (idx < NNODES) {
        g_rowstart[idx] = excl;
        g_cursor[idx]   = excl;   // reuse as scatter cursor
    }
}

__global__ void k_fill(const int* __restrict__ src, const int* __restrict__ dst,
                       const float* __restrict__ w) {
    int e = blockIdx.x * blockDim.x + threadIdx.x;
    if (e < NEDGES) {
        int d = dst[e];
        int pos = atomicAdd(&g_cursor[d], 1);
        g_col[pos]  = src[e];
        g_wval[pos] = w[e];
    }
}

// ---------------- W' = beta*W + (1-beta)*I ----------------
__global__ void k_prepw(const float* __restrict__ conv_w, Betas bb) {
    int idx = blockIdx.x * blockDim.x + threadIdx.x;
    if (idx >= NLAYERS * DH * DH) return;
    int l = idx >> 14;          // / 16384
    int rem = idx & 16383;
    int k = rem >> 7, n = rem & 127;
    float beta = bb.b[l];
    float v = beta * conv_w[idx];
    if (k == n) v += 1.0f - beta;
    g_Wp[idx] = v;
}

// ---------------- spmm: sup = 0.9 * (A_hat x) + 0.1 * h0 ----------------
__global__ __launch_bounds__(256) void k_spmm() {
    int gw = (blockIdx.x * blockDim.x + threadIdx.x) >> 5;  // warp per node
    int lane = threadIdx.x & 31;
    if (gw >= NNODES) return;
    int s = g_rowstart[gw];
    int e = g_rowstart[gw + 1];
    float4 acc = make_float4(0.f, 0.f, 0.f, 0.f);
    for (int base = s; base < e; base += 32) {
        int i = base + lane;
        int c  = (i < e) ? g_col[i]  : 0;
        float w = (i < e) ? g_wval[i] : 0.f;
        int cnt = min(32, e - base);
        for (int j = 0; j < cnt; j++) {
            int   cj = __shfl_sync(0xffffffffu, c, j);
            float wj = __shfl_sync(0xffffffffu, w, j);
            float4 xv = *reinterpret_cast<const float4*>(g_x + (size_t)cj * DH + lane * 4);
            acc.x += wj * xv.x;
            acc.y += wj * xv.y;
            acc.z += wj * xv.z;
            acc.w += wj * xv.w;
        }
    }
    float4 h = *reinterpret_cast<const float4*>(g_h0 + (size_t)gw * DH + lane * 4);
    float4 o;
    o.x = 0.9f * acc.x + 0.1f * h.x;
    o.y = 0.9f * acc.y + 0.1f * h.y;
    o.z = 0.9f * acc.z + 0.1f * h.z;
    o.w = 0.9f * acc.w + 0.1f * h.w;
    *reinterpret_cast<float4*>(g_sup + (size_t)gw * DH + lane * 4) = o;
}

// ---------------- tiled SGEMM: out = relu(A @ B [+ bias]) ----------------
// BM=128, BN=128(=H), BK=16, 256 threads, 8x8 per thread.
// MODE 0: A=features (param), B=w_fc0 (param), +bias, writes g_x AND g_h0.
// MODE 1: A=g_sup, B=g_Wp[layer], no bias, writes g_x.
template <int KTOT, int MODE>
__global__ __launch_bounds__(256) void k_gemm(const float* __restrict__ Ain,
                                              const float* __restrict__ Bin,
                                              const float* __restrict__ bias,
                                              int layer) {
    const int AS_LD = 132;
    __shared__ float As[16 * AS_LD];
    __shared__ float Bs[16 * 128];

    const float* A = (MODE == 1) ? g_sup : Ain;
    const float* B = (MODE == 1) ? (g_Wp + (size_t)layer * DH * DH) : Bin;

    int tid = threadIdx.x;
    int tx = tid & 15;          // n-direction: 16 threads * 8
    int ty = tid >> 4;          // m-direction: 16 threads * 8
    int row0 = blockIdx.x * 128;

    float acc[8][8];
#pragma unroll
    for (int i = 0; i < 8; i++)
#pragma unroll
        for (int j = 0; j < 8; j++) acc[i][j] = 0.f;

    for (int k0 = 0; k0 < KTOT; k0 += 16) {
        // load A tile (128 x 16), store transposed As[k][m]
#pragma unroll
        for (int it = 0; it < 2; it++) {
            int idx = tid + it * 256;      // 0..511
            int r = idx >> 2;              // 0..127
            int q = idx & 3;               // 0..3 (4 floats each)
            int grow = row0 + r;
            float4 v = make_float4(0.f, 0.f, 0.f, 0.f);
            if (grow < NNODES)
                v = *reinterpret_cast<const float4*>(A + (size_t)grow * KTOT + k0 + q * 4);
            As[(q * 4 + 0) * AS_LD + r] = v.x;
            As[(q * 4 + 1) * AS_LD + r] = v.y;
            As[(q * 4 + 2) * AS_LD + r] = v.z;
            As[(q * 4 + 3) * AS_LD + r] = v.w;
        }
        // load B tile (16 x 128)
#pragma unroll
        for (int it = 0; it < 2; it++) {
            int idx = tid + it * 256;      // 0..511
            int kk = idx >> 5;             // 0..15
            int nq = idx & 31;             // 0..31 (float4)
            *reinterpret_cast<float4*>(Bs + kk * 128 + nq * 4) =
                *reinterpret_cast<const float4*>(B + (size_t)(k0 + kk) * 128 + nq * 4);
        }
        __syncthreads();

#pragma unroll
        for (int k = 0; k < 16; k++) {
            float a[8], b[8];
#pragma unroll
            for (int i = 0; i < 8; i++) a[i] = As[k * AS_LD + ty * 8 + i];
#pragma unroll
            for (int j = 0; j < 8; j++) b[j] = Bs[k * 128 + tx * 8 + j];
#pragma unroll
            for (int i = 0; i < 8; i++)
#pragma unroll
                for (int j = 0; j < 8; j++) acc[i][j] += a[i] * b[j];
        }
        __syncthreads();
    }

#pragma unroll
    for (int i = 0; i < 8; i++) {
        int grow = row0 + ty * 8 + i;
        if (grow < NNODES) {
#pragma unroll
            for (int j = 0; j < 8; j++) {
                int n = tx * 8 + j;
                float c = acc[i][j];
                if (MODE == 0) c += bias[n];
                c = fmaxf(c, 0.f);
                g_x[(size_t)grow * DH + n] = c;
                if (MODE == 0) g_h0[(size_t)grow * DH + n] = c;
            }
        }
    }
}

// ---------------- fc1: out = g_x @ W + bias  ([N,128]x[128,40]) ----------------
__global__ __launch_bounds__(256) void k_fc1(const float* __restrict__ W,
                                             const float* __restrict__ bias,
                                             float* __restrict__ out) {
    __shared__ float xs[32 * 132];
    __shared__ float Ws[128 * 40];
    int tid = threadIdx.x;
    int row0 = blockIdx.x * 32;

    for (int i = tid; i < 128 * 40; i += 256) Ws[i] = W[i];
#pragma unroll
    for (int it = 0; it < 4; it++) {
        int idx = tid + it * 256;      // 0..1023
        int r = idx >> 5;              // 0..31
        int q = idx & 31;              // float4 index
        int grow = row0 + r;
        float4 v = make_float4(0.f, 0.f, 0.f, 0.f);
        if (grow < NNODES)
            v = *reinterpret_cast<const float4*>(g_x + (size_t)grow * DH + q * 4);
        xs[r * 132 + q * 4 + 0] = v.x;
        xs[r * 132 + q * 4 + 1] = v.y;
        xs[r * 132 + q * 4 + 2] = v.z;
        xs[r * 132 + q * 4 + 3] = v.w;
    }
    __syncthreads();

    int r  = tid >> 3;       // 0..31 (row within tile)
    int cg = tid & 7;        // 0..7 (5 cols each)
    int c0 = cg * 5;
    float acc[5] = {0.f, 0.f, 0.f, 0.f, 0.f};
#pragma unroll 4
    for (int k = 0; k < 128; k++) {
        float a = xs[r * 132 + k];
#pragma unroll
        for (int j = 0; j < 5; j++) acc[j] += a * Ws[k * 40 + c0 + j];
    }
    int grow = row0 + r;
    if (grow < NNODES) {
#pragma unroll
        for (int j = 0; j < 5; j++)
            out[(size_t)grow * DC + c0 + j] = acc[j] + bias[c0 + j];
    }
}

// ---------------- host ----------------
extern "C" void kernel_launch(void* const* d_in, const int* in_sizes, int n_in,
                              void* d_out, int out_size) {
    const float* features  = (const float*)d_in[0];
    const int*   edge_index= (const int*)  d_in[1];
    const float* norm_A    = (const float*)d_in[2];
    const float* w_fc0     = (const float*)d_in[3];
    const float* b_fc0     = (const float*)d_in[4];
    const float* conv_w    = (const float*)d_in[5];
    const float* w_fc1     = (const float*)d_in[6];
    const float* b_fc1     = (const float*)d_in[7];
    float* out = (float*)d_out;

    const int* srcp = edge_index;
    const int* dstp = edge_index + NEDGES;

    // CSR build
    k_zero<<<(NNODES + 255) / 256, 256>>>();
    k_hist<<<(NEDGES + 255) / 256, 256>>>(dstp);
    k_blocksum<<<NSCANB, 1024>>>();
    k_scan_small<<<1, 1>>>();
    k_scan_final<<<NSCANB, 1024>>>();
    k_fill<<<(NEDGES + 255) / 256, 256>>>(srcp, dstp, norm_A);

    // fold identity mapping into layer weights
    Betas bb;
    for (int l = 0; l < NLAYERS; l++)
        bb.b[l] = (float)log(0.5 / (double)(l + 1) + 1.0);
    k_prepw<<<(NLAYERS * DH * DH + 255) / 256, 256>>>(conv_w, bb);

    // fc0: x = h0 = relu(features @ w_fc0 + b)
    const int GEMM_BLOCKS = (NNODES + 127) / 128;   // 391
    k_gemm<DIN, 0><<<GEMM_BLOCKS, 256>>>(features, w_fc0, b_fc0, 0);

    // 8 GCNII layers
    const int SPMM_BLOCKS = (NNODES * 32 + 255) / 256;  // 6250
    for (int l = 0; l < NLAYERS; l++) {
        k_spmm<<<SPMM_BLOCKS, 256>>>();
        k_gemm<DH, 1><<<GEMM_BLOCKS, 256>>>(nullptr, nullptr, nullptr, l);
    }

    // fc1
    k_fc1<<<(NNODES + 31) / 32, 256>>>(w_fc1, b_fc1, out);
}